// round 12
// baseline (speedup 1.0000x reference)
#include <cuda_runtime.h>
#include <cuda_bf16.h>
#include <math.h>

#define NGRID 128
#define NDIR  128
#define NK    25
#define P_TOTAL (NGRID*NGRID*NGRID)
#define BLOCK 128
#define CHUNK 16
#define NCH   (NDIR/CHUNK)

#define SCALE_LN2  0.05344600f      // (pi^2/128) * ln2
#define K16LOG2E   23.0831207f      // 16*log2(e)
#define HMIN       0.00200033f      // acos(0.999)^2

// h(x) ~ acos(x)^2, degree-6 monomial
#define A0f  2.46613525f
#define A1f -3.12988405f
#define A2f  0.95262957f
#define A3f -0.41216060f
#define A4f  0.16084943f
#define A5f -0.04312660f
#define A6f  0.00555700f

#define BSTRIDE 132   // bases smem row stride
#define LSTRIDE 40    // lg smem row stride (32 cols + 8 pad; conflict-free)

typedef unsigned long long u64;
typedef unsigned int u32;

__device__ __forceinline__ float ex2f(float x) {
    float r; asm("ex2.approx.ftz.f32 %0, %1;" : "=f"(r) : "f"(x)); return r;
}
__device__ __forceinline__ float lg2f(float x) {
    float r; asm("lg2.approx.ftz.f32 %0, %1;" : "=f"(r) : "f"(x)); return r;
}
__device__ __forceinline__ u64 pack2(float lo, float hi) {
    u64 r; asm("mov.b64 %0, {%1, %2};" : "=l"(r) : "f"(lo), "f"(hi)); return r;
}
__device__ __forceinline__ void unpack2(u64 v, float& lo, float& hi) {
    asm("mov.b64 {%0, %1}, %2;" : "=f"(lo), "=f"(hi) : "l"(v));
}
__device__ __forceinline__ u64 fma2(u64 a, u64 b, u64 c) {
    u64 d; asm("fma.rn.f32x2 %0, %1, %2, %3;" : "=l"(d) : "l"(a), "l"(b), "l"(c)); return d;
}
__device__ __forceinline__ u64 mul2(u64 a, u64 b) {
    u64 d; asm("mul.rn.f32x2 %0, %1, %2;" : "=l"(d) : "l"(a), "l"(b)); return d;
}
__device__ __forceinline__ u32 tf32b(float x) {
    u32 r; asm("cvt.rna.tf32.f32 %0, %1;" : "=r"(r) : "f"(x)); return r;
}
__device__ __forceinline__ void mma_tf32(float& c0, float& c1, float& c2, float& c3,
                                         u32 a0, u32 a1, u32 a2, u32 a3,
                                         u32 b0, u32 b1) {
    asm("mma.sync.aligned.m16n8k8.row.col.f32.tf32.tf32.f32 "
        "{%0,%1,%2,%3}, {%4,%5,%6,%7}, {%8,%9}, {%0,%1,%2,%3};"
        : "+f"(c0), "+f"(c1), "+f"(c2), "+f"(c3)
        : "r"(a0), "r"(a1), "r"(a2), "r"(a3), "r"(b0), "r"(b1));
}

#define DECLARE_POLY_CONSTS                                                        \
    const u64 PA0 = pack2(A0f, A0f), PA1 = pack2(A1f, A1f), PA2 = pack2(A2f, A2f); \
    const u64 PA3 = pack2(A3f, A3f), PA4 = pack2(A4f, A4f), PA5 = pack2(A5f, A5f); \
    const u64 PA6 = pack2(A6f, A6f);

// Direction-PAIR weight args for one point: dpi indexes pairs (2*dpi, 2*dpi+1)
#define DIRP_ARGS(dpi, a0v, a1v)                                               \
    {                                                                          \
        ulonglong2 u1 = *reinterpret_cast<const ulonglong2*>(&D1p[dpi]);       \
        ulonglong2 u2 = *reinterpret_cast<const ulonglong2*>(&D2p[dpi]);       \
        u64 dp2 = fma2(u1.x, nxx, fma2(u1.y, nyy, mul2(u2.x, nzz)));           \
        u64 h2 = fma2(PA6, dp2, PA5);                                          \
        h2 = fma2(h2, dp2, PA4);                                               \
        h2 = fma2(h2, dp2, PA3);                                               \
        h2 = fma2(h2, dp2, PA2);                                               \
        h2 = fma2(h2, dp2, PA1);                                               \
        h2 = fma2(h2, dp2, PA0);                                               \
        float h0, h1; unpack2(h2, h0, h1);                                     \
        float lsw0, lsw1; unpack2(u2.y, lsw0, lsw1);                           \
        a0v = fmaf(fmaxf(h0, HMIN), -K16LOG2E, lsw0);                          \
        a1v = fmaf(fmaxf(h1, HMIN), -K16LOG2E, lsw1);                          \
    }

__global__ __launch_bounds__(BLOCK, 6)
void sh_nearfield_kernel(const float* __restrict__ bases,
                         const float* __restrict__ th,
                         const float* __restrict__ ph,
                         const int*   __restrict__ iternum_p,
                         int B,
                         float* __restrict__ out)
{
    __shared__ __align__(16) float4 D1p[NDIR / 2];   // {vx(2i),vx(2i+1),vy(2i),vy(2i+1)}
    __shared__ __align__(16) float4 D2p[NDIR / 2];   // {vz(2i),vz(2i+1),lsw(2i),lsw(2i+1)}
    __shared__ u32 basesM[32 * BSTRIDE];
    __shared__ u32 lgS[4 * CHUNK * LSTRIDE];

    const int tid  = threadIdx.x;
    const int w    = tid >> 5;
    const int lane = tid & 31;
    const int g    = lane >> 2;
    const int t4   = lane & 3;

    if (tid < NDIR / 2) {
        int d0 = 2 * tid, d1 = 2 * tid + 1;
        float t0 = th[d0], p0f = ph[d0];
        float t1 = th[d1], p1f = ph[d1];
        float st0 = sinf(t0), ct0 = cosf(t0), sp0 = sinf(p0f), cp0 = cosf(p0f);
        float st1 = sinf(t1), ct1 = cosf(t1), sp1 = sinf(p1f), cp1 = cosf(p1f);
        D1p[tid] = make_float4(st0 * sp0, st1 * sp1, ct0, ct1);
        D2p[tid] = make_float4(st0 * cp0, st1 * cp1, log2f(st0), log2f(st1));
    }
    for (int i = tid; i < 32 * NDIR; i += BLOCK) {
        int m = i >> 7, d = i & (NDIR - 1);
        float v = (m < NK) ? bases[m * NDIR + d] : 0.0f;
        basesM[m * BSTRIDE + d] = tf32b(v);
    }
    __syncthreads();

    const int b = blockIdx.z;
    const int p = blockIdx.x * BLOCK + tid;   // one point per thread

    const int iternum = *iternum_p;
    const float ph0 = (float)((double)(iternum * B + b) * 2.0 * 3.1415926 / 131.0);
    const float lx = sinf(ph0) * 0.3f;
    const float lz = 0.4f;
    const float step = 2.0f / 127.0f;

    float sv;
    u64 nxx, nyy, nzz;
    {
        float x = -1.0f + (p & (NGRID - 1)) * step;
        float y = -1.0f + ((p >> 7) & (NGRID - 1)) * step;
        float z = -1.0f + (p >> 14) * step;
        float ldx = lx - x, ldy = -y, ldz = lz - z;
        float s = fmaf(ldx, ldx, fmaf(ldy, ldy, fmaf(ldz, ldz, 1e-4f)));
        float rn = rsqrtf(s);
        float nx = ldx * rn, ny = ldy * rn, nz = ldz * rn;
        nxx = pack2(nx, nx);
        nyy = pack2(ny, ny);
        nzz = pack2(nz, nz);
        sv = s;
    }

    DECLARE_POLY_CONSTS;

    // ---- Pass 1: normalization sum (64 dir-pairs, unroll 4) ----
    float sum = 0.0f;
    #pragma unroll 4
    for (int dpi = 0; dpi < NDIR / 2; ++dpi) {
        float a0, a1;
        DIRP_ARGS(dpi, a0, a1);
        sum += ex2f(a0);
        sum += ex2f(a1);
    }
    const float invs = 4.0f / (sv * sum);

    // ---- Pass 2: weights -> lg -> tensor-core projection ----
    float C[2][4][4];
    #pragma unroll
    for (int mt = 0; mt < 2; ++mt)
        #pragma unroll
        for (int nt = 0; nt < 4; ++nt)
            #pragma unroll
            for (int q = 0; q < 4; ++q) C[mt][nt][q] = 0.0f;

    u32* lgW = &lgS[w * CHUNK * LSTRIDE];

    for (int ch = 0; ch < NCH; ++ch) {
        #pragma unroll 4
        for (int dl = 0; dl < CHUNK / 2; ++dl) {       // 8 dir-pairs = 16 dirs
            int dpi = ch * (CHUNK / 2) + dl;
            float a0, a1;
            DIRP_ARGS(dpi, a0, a1);
            float w0 = ex2f(a0);
            float w1 = ex2f(a1);
            float lg0 = lg2f(fmaf(w0, invs, 1e-4f));
            float lg1 = lg2f(fmaf(w1, invs, 1e-4f));
            lgW[(2 * dl)     * LSTRIDE + lane] = tf32b(lg0);
            lgW[(2 * dl + 1) * LSTRIDE + lane] = tf32b(lg1);
        }
        __syncwarp();

        #pragma unroll
        for (int ks = 0; ks < 2; ++ks) {
            const int kcol = ch * CHUNK + ks * 8 + t4;
            u32 a[2][4];
            #pragma unroll
            for (int mt = 0; mt < 2; ++mt) {
                int base = (g + 16 * mt) * BSTRIDE + kcol;
                a[mt][0] = basesM[base];
                a[mt][1] = basesM[base + 8 * BSTRIDE];
                a[mt][2] = basesM[base + 4];
                a[mt][3] = basesM[base + 8 * BSTRIDE + 4];
            }
            #pragma unroll
            for (int nt = 0; nt < 4; ++nt) {
                int bb = (ks * 8 + t4) * LSTRIDE + 8 * nt + g;
                u32 b0 = lgW[bb];
                u32 b1 = lgW[bb + 4 * LSTRIDE];
                mma_tf32(C[0][nt][0], C[0][nt][1], C[0][nt][2], C[0][nt][3],
                         a[0][0], a[0][1], a[0][2], a[0][3], b0, b1);
                mma_tf32(C[1][nt][0], C[1][nt][1], C[1][nt][2], C[1][nt][3],
                         a[1][0], a[1][1], a[1][2], a[1][3], b0, b1);
            }
        }
        __syncwarp();
    }

    // ---- Epilogue ----
    const size_t PP = (size_t)P_TOTAL;
    float* ob = out + (size_t)b * 75 * PP;
    const int pb = blockIdx.x * BLOCK + 32 * w;

    #pragma unroll
    for (int mt = 0; mt < 2; ++mt) {
        #pragma unroll
        for (int nt = 0; nt < 4; ++nt) {
            const int pcol = pb + 8 * nt + 2 * t4;
            const int r0 = 16 * mt + g;
            const int r1 = r0 + 8;
            float2 v0 = make_float2(C[mt][nt][0] * SCALE_LN2, C[mt][nt][1] * SCALE_LN2);
            float2 v1 = make_float2(C[mt][nt][2] * SCALE_LN2, C[mt][nt][3] * SCALE_LN2);
            #pragma unroll
            for (int c = 0; c < 3; ++c) {
                *reinterpret_cast<float2*>(ob + (size_t)(3 * r0 + c) * PP + pcol) = v0;
            }
            if (r1 < NK) {
                #pragma unroll
                for (int c = 0; c < 3; ++c) {
                    *reinterpret_cast<float2*>(ob + (size_t)(3 * r1 + c) * PP + pcol) = v1;
                }
            }
        }
    }
}

extern "C" void kernel_launch(void* const* d_in, const int* in_sizes, int n_in,
                              void* d_out, int out_size)
{
    const float* bases = (const float*)d_in[0];
    const float* th    = (const float*)d_in[1];
    const float* ph    = (const float*)d_in[2];
    const int*   itn   = (const int*)d_in[3];
    const int    B     = in_sizes[4];

    dim3 grid(P_TOTAL / BLOCK, 1, (unsigned)B);
    sh_nearfield_kernel<<<grid, BLOCK>>>(bases, th, ph, itn, B, (float*)d_out);
}

// round 13
// speedup vs baseline: 1.5682x; 1.5682x over previous
#include <cuda_runtime.h>
#include <cuda_bf16.h>
#include <math.h>

#define NGRID 128
#define NDIR  128
#define NK    25
#define P_TOTAL (NGRID*NGRID*NGRID)
#define BLOCK 128
#define CHUNK 16
#define NCH   (NDIR/CHUNK)

#define SCALE_LN2  0.05344600f      // (pi^2/128) * ln2
#define K16LOG2E   23.0831207f      // 16*log2(e)
#define HMIN       0.00200033f      // acos(0.999)^2

// h(x) ~ acos(x)^2, degree-6 monomial
#define A0f  2.46613525f
#define A1f -3.12988405f
#define A2f  0.95262957f
#define A3f -0.41216060f
#define A4f  0.16084943f
#define A5f -0.04312660f
#define A6f  0.00555700f

#define BSTRIDE 132   // bases smem row stride
#define LSTRIDE 40    // lg smem row stride (32 cols + 8 pad; conflict-free)

typedef unsigned long long u64;
typedef unsigned int u32;

// sign of out_k under y-mirror: (-1)^(n+|m|), k = 0..24
__constant__ float SGN25[25] = {
    1.f,
    1.f,-1.f,1.f,
    1.f,-1.f,1.f,-1.f,1.f,
    1.f,-1.f,1.f,-1.f,1.f,-1.f,1.f,
    1.f,-1.f,1.f,-1.f,1.f,-1.f,1.f,-1.f,1.f
};

__device__ __forceinline__ float ex2f(float x) {
    float r; asm("ex2.approx.ftz.f32 %0, %1;" : "=f"(r) : "f"(x)); return r;
}
__device__ __forceinline__ float lg2f(float x) {
    float r; asm("lg2.approx.ftz.f32 %0, %1;" : "=f"(r) : "f"(x)); return r;
}
__device__ __forceinline__ u64 pack2(float lo, float hi) {
    u64 r; asm("mov.b64 %0, {%1, %2};" : "=l"(r) : "f"(lo), "f"(hi)); return r;
}
__device__ __forceinline__ void unpack2(u64 v, float& lo, float& hi) {
    asm("mov.b64 {%0, %1}, %2;" : "=f"(lo), "=f"(hi) : "l"(v));
}
__device__ __forceinline__ u64 fma2(u64 a, u64 b, u64 c) {
    u64 d; asm("fma.rn.f32x2 %0, %1, %2, %3;" : "=l"(d) : "l"(a), "l"(b), "l"(c)); return d;
}
__device__ __forceinline__ u64 mul2(u64 a, u64 b) {
    u64 d; asm("mul.rn.f32x2 %0, %1, %2;" : "=l"(d) : "l"(a), "l"(b)); return d;
}
__device__ __forceinline__ u32 tf32b(float x) {
    u32 r; asm("cvt.rna.tf32.f32 %0, %1;" : "=r"(r) : "f"(x)); return r;
}
__device__ __forceinline__ void mma_tf32(float& c0, float& c1, float& c2, float& c3,
                                         u32 a0, u32 a1, u32 a2, u32 a3,
                                         u32 b0, u32 b1) {
    asm("mma.sync.aligned.m16n8k8.row.col.f32.tf32.tf32.f32 "
        "{%0,%1,%2,%3}, {%4,%5,%6,%7}, {%8,%9}, {%0,%1,%2,%3};"
        : "+f"(c0), "+f"(c1), "+f"(c2), "+f"(c3)
        : "r"(a0), "r"(a1), "r"(a2), "r"(a3), "r"(b0), "r"(b1));
}

#define DECLARE_POLY_CONSTS                                                        \
    const u64 PA0 = pack2(A0f, A0f), PA1 = pack2(A1f, A1f), PA2 = pack2(A2f, A2f); \
    const u64 PA3 = pack2(A3f, A3f), PA4 = pack2(A4f, A4f), PA5 = pack2(A5f, A5f); \
    const u64 PA6 = pack2(A6f, A6f);

#define DIRP_ARGS(dpi, a0v, a1v)                                               \
    {                                                                          \
        ulonglong2 u1 = *reinterpret_cast<const ulonglong2*>(&D1p[dpi]);       \
        ulonglong2 u2 = *reinterpret_cast<const ulonglong2*>(&D2p[dpi]);       \
        u64 dp2 = fma2(u1.x, nxx, fma2(u1.y, nyy, mul2(u2.x, nzz)));           \
        u64 h2 = fma2(PA6, dp2, PA5);                                          \
        h2 = fma2(h2, dp2, PA4);                                               \
        h2 = fma2(h2, dp2, PA3);                                               \
        h2 = fma2(h2, dp2, PA2);                                               \
        h2 = fma2(h2, dp2, PA1);                                               \
        h2 = fma2(h2, dp2, PA0);                                               \
        float h0, h1; unpack2(h2, h0, h1);                                     \
        float lsw0, lsw1; unpack2(u2.y, lsw0, lsw1);                           \
        a0v = fmaf(fmaxf(h0, HMIN), -K16LOG2E, lsw0);                          \
        a1v = fmaf(fmaxf(h1, HMIN), -K16LOG2E, lsw1);                          \
    }

__global__ __launch_bounds__(BLOCK, 6)
void sh_nearfield_kernel(const float* __restrict__ bases,
                         const float* __restrict__ th,
                         const float* __restrict__ ph,
                         const int*   __restrict__ iternum_p,
                         int B,
                         float* __restrict__ out)
{
    __shared__ __align__(16) float4 D1p[NDIR / 2];
    __shared__ __align__(16) float4 D2p[NDIR / 2];
    __shared__ u32 basesM[32 * BSTRIDE];
    __shared__ u32 lgS[4 * CHUNK * LSTRIDE];

    const int tid  = threadIdx.x;
    const int w    = tid >> 5;
    const int lane = tid & 31;
    const int g    = lane >> 2;
    const int t4   = lane & 3;

    if (tid < NDIR / 2) {
        int d0 = 2 * tid, d1 = 2 * tid + 1;
        float t0 = th[d0], p0f = ph[d0];
        float t1 = th[d1], p1f = ph[d1];
        float st0 = sinf(t0), ct0 = cosf(t0), sp0 = sinf(p0f), cp0 = cosf(p0f);
        float st1 = sinf(t1), ct1 = cosf(t1), sp1 = sinf(p1f), cp1 = cosf(p1f);
        D1p[tid] = make_float4(st0 * sp0, st1 * sp1, ct0, ct1);
        D2p[tid] = make_float4(st0 * cp0, st1 * cp1, log2f(st0), log2f(st1));
    }
    for (int i = tid; i < 32 * NDIR; i += BLOCK) {
        int m = i >> 7, d = i & (NDIR - 1);
        float v = (m < NK) ? bases[m * NDIR + d] : 0.0f;
        basesM[m * BSTRIDE + d] = tf32b(v);
    }
    __syncthreads();

    const int b = blockIdx.z;
    // half-grid point: iy in [0, 64)
    const int ph_idx = blockIdx.x * BLOCK + tid;
    const int ix = ph_idx & (NGRID - 1);
    const int iy = (ph_idx >> 7) & 63;
    const int iz = ph_idx >> 13;

    const int iternum = *iternum_p;
    const float ph0 = (float)((double)(iternum * B + b) * 2.0 * 3.1415926 / 131.0);
    const float lx = sinf(ph0) * 0.3f;
    const float lz = 0.4f;
    const float step = 2.0f / 127.0f;

    float sv;
    u64 nxx, nyy, nzz;
    {
        float x = -1.0f + ix * step;
        float y = -1.0f + iy * step;
        float z = -1.0f + iz * step;
        float ldx = lx - x, ldy = -y, ldz = lz - z;
        float s = fmaf(ldx, ldx, fmaf(ldy, ldy, fmaf(ldz, ldz, 1e-4f)));
        float rn = rsqrtf(s);
        float nx = ldx * rn, ny = ldy * rn, nz = ldz * rn;
        nxx = pack2(nx, nx);
        nyy = pack2(ny, ny);
        nzz = pack2(nz, nz);
        sv = s;
    }

    DECLARE_POLY_CONSTS;

    // ---- Pass 1: normalization sum ----
    float sum = 0.0f;
    #pragma unroll 4
    for (int dpi = 0; dpi < NDIR / 2; ++dpi) {
        float a0, a1;
        DIRP_ARGS(dpi, a0, a1);
        sum += ex2f(a0);
        sum += ex2f(a1);
    }
    const float invs = 4.0f / (sv * sum);

    // ---- Pass 2: weights -> lg -> tensor-core projection ----
    float C[2][4][4];
    #pragma unroll
    for (int mt = 0; mt < 2; ++mt)
        #pragma unroll
        for (int nt = 0; nt < 4; ++nt)
            #pragma unroll
            for (int q = 0; q < 4; ++q) C[mt][nt][q] = 0.0f;

    u32* lgW = &lgS[w * CHUNK * LSTRIDE];

    for (int ch = 0; ch < NCH; ++ch) {
        #pragma unroll 4
        for (int dl = 0; dl < CHUNK / 2; ++dl) {
            int dpi = ch * (CHUNK / 2) + dl;
            float a0, a1;
            DIRP_ARGS(dpi, a0, a1);
            float w0 = ex2f(a0);
            float w1 = ex2f(a1);
            float lg0 = lg2f(fmaf(w0, invs, 1e-4f));
            float lg1 = lg2f(fmaf(w1, invs, 1e-4f));
            lgW[(2 * dl)     * LSTRIDE + lane] = tf32b(lg0);
            lgW[(2 * dl + 1) * LSTRIDE + lane] = tf32b(lg1);
        }
        __syncwarp();

        #pragma unroll
        for (int ks = 0; ks < 2; ++ks) {
            const int kcol = ch * CHUNK + ks * 8 + t4;
            u32 a[2][4];
            #pragma unroll
            for (int mt = 0; mt < 2; ++mt) {
                int base = (g + 16 * mt) * BSTRIDE + kcol;
                a[mt][0] = basesM[base];
                a[mt][1] = basesM[base + 8 * BSTRIDE];
                a[mt][2] = basesM[base + 4];
                a[mt][3] = basesM[base + 8 * BSTRIDE + 4];
            }
            #pragma unroll
            for (int nt = 0; nt < 4; ++nt) {
                int bb = (ks * 8 + t4) * LSTRIDE + 8 * nt + g;
                u32 b0 = lgW[bb];
                u32 b1 = lgW[bb + 4 * LSTRIDE];
                mma_tf32(C[0][nt][0], C[0][nt][1], C[0][nt][2], C[0][nt][3],
                         a[0][0], a[0][1], a[0][2], a[0][3], b0, b1);
                mma_tf32(C[1][nt][0], C[1][nt][1], C[1][nt][2], C[1][nt][3],
                         a[1][0], a[1][1], a[1][2], a[1][3], b0, b1);
            }
        }
        __syncwarp();
    }

    // ---- Epilogue: write iy row and mirrored (127-iy) row with parity signs ----
    const size_t PP = (size_t)P_TOTAL;
    float* ob = out + (size_t)b * 75 * PP;

    const int pb   = blockIdx.x * BLOCK + 32 * w;    // warp's half-index base
    const int ixw  = pb & (NGRID - 1);
    const int iyzw = pb >> 7;
    const int iyv  = iyzw & 63;
    const int izv  = iyzw >> 6;
    const size_t o_lo = (size_t)izv * (NGRID * NGRID) + (size_t)iyv * NGRID + ixw;
    const size_t o_hi = (size_t)izv * (NGRID * NGRID) + (size_t)(127 - iyv) * NGRID + ixw;

    #pragma unroll
    for (int mt = 0; mt < 2; ++mt) {
        #pragma unroll
        for (int nt = 0; nt < 4; ++nt) {
            const int po = 8 * nt + 2 * t4;
            const int r0 = 16 * mt + g;
            const int r1 = r0 + 8;
            float sg0 = SGN25[r0];
            float2 v0  = make_float2(C[mt][nt][0] * SCALE_LN2, C[mt][nt][1] * SCALE_LN2);
            float2 v0m = make_float2(v0.x * sg0, v0.y * sg0);
            #pragma unroll
            for (int c = 0; c < 3; ++c) {
                size_t ro = (size_t)(3 * r0 + c) * PP;
                *reinterpret_cast<float2*>(ob + ro + o_lo + po) = v0;
                *reinterpret_cast<float2*>(ob + ro + o_hi + po) = v0m;
            }
            if (r1 < NK) {
                float sg1 = SGN25[r1];
                float2 v1  = make_float2(C[mt][nt][2] * SCALE_LN2, C[mt][nt][3] * SCALE_LN2);
                float2 v1m = make_float2(v1.x * sg1, v1.y * sg1);
                #pragma unroll
                for (int c = 0; c < 3; ++c) {
                    size_t ro = (size_t)(3 * r1 + c) * PP;
                    *reinterpret_cast<float2*>(ob + ro + o_lo + po) = v1;
                    *reinterpret_cast<float2*>(ob + ro + o_hi + po) = v1m;
                }
            }
        }
    }
}

extern "C" void kernel_launch(void* const* d_in, const int* in_sizes, int n_in,
                              void* d_out, int out_size)
{
    const float* bases = (const float*)d_in[0];
    const float* th    = (const float*)d_in[1];
    const float* ph    = (const float*)d_in[2];
    const int*   itn   = (const int*)d_in[3];
    const int    B     = in_sizes[4];

    dim3 grid(P_TOTAL / (BLOCK * 2), 1, (unsigned)B);
    sh_nearfield_kernel<<<grid, BLOCK>>>(bases, th, ph, itn, B, (float*)d_out);
}

// round 14
// speedup vs baseline: 1.6113x; 1.0275x over previous
#include <cuda_runtime.h>
#include <cuda_bf16.h>
#include <math.h>

#define NGRID 128
#define NDIR  128
#define NK    25
#define P_TOTAL (NGRID*NGRID*NGRID)
#define BLOCK 128
#define CHUNK 16
#define NCH   (NDIR/CHUNK)

#define SCALE_LN2  0.05344600f      // (pi^2/128) * ln2
#define K16LOG2E   23.0831207f      // 16*log2(e)
#define HMIN       0.00200033f      // acos(0.999)^2

// h(x) ~ acos(x)^2, degree-6 monomial
#define A0f  2.46613525f
#define A1f -3.12988405f
#define A2f  0.95262957f
#define A3f -0.41216060f
#define A4f  0.16084943f
#define A5f -0.04312660f
#define A6f  0.00555700f

#define BSTRIDE 132   // bases smem row stride
#define LSTRIDE 40    // lg smem row stride (32 cols + 8 pad; conflict-free)

typedef unsigned long long u64;
typedef unsigned int u32;

// sign of out_k under y-mirror: (-1)^(n+|m|), k = 0..24
__constant__ float SGN25[25] = {
    1.f,
    1.f,-1.f,1.f,
    1.f,-1.f,1.f,-1.f,1.f,
    1.f,-1.f,1.f,-1.f,1.f,-1.f,1.f,
    1.f,-1.f,1.f,-1.f,1.f,-1.f,1.f,-1.f,1.f
};

__device__ __forceinline__ float ex2f(float x) {
    float r; asm("ex2.approx.ftz.f32 %0, %1;" : "=f"(r) : "f"(x)); return r;
}
__device__ __forceinline__ float lg2f(float x) {
    float r; asm("lg2.approx.ftz.f32 %0, %1;" : "=f"(r) : "f"(x)); return r;
}
__device__ __forceinline__ u64 pack2(float lo, float hi) {
    u64 r; asm("mov.b64 %0, {%1, %2};" : "=l"(r) : "f"(lo), "f"(hi)); return r;
}
__device__ __forceinline__ void unpack2(u64 v, float& lo, float& hi) {
    asm("mov.b64 {%0, %1}, %2;" : "=f"(lo), "=f"(hi) : "l"(v));
}
__device__ __forceinline__ u64 fma2(u64 a, u64 b, u64 c) {
    u64 d; asm("fma.rn.f32x2 %0, %1, %2, %3;" : "=l"(d) : "l"(a), "l"(b), "l"(c)); return d;
}
__device__ __forceinline__ u64 mul2(u64 a, u64 b) {
    u64 d; asm("mul.rn.f32x2 %0, %1, %2;" : "=l"(d) : "l"(a), "l"(b)); return d;
}
__device__ __forceinline__ u32 tf32b(float x) {
    u32 r; asm("cvt.rna.tf32.f32 %0, %1;" : "=r"(r) : "f"(x)); return r;
}
__device__ __forceinline__ void mma_tf32(float& c0, float& c1, float& c2, float& c3,
                                         u32 a0, u32 a1, u32 a2, u32 a3,
                                         u32 b0, u32 b1) {
    asm("mma.sync.aligned.m16n8k8.row.col.f32.tf32.tf32.f32 "
        "{%0,%1,%2,%3}, {%4,%5,%6,%7}, {%8,%9}, {%0,%1,%2,%3};"
        : "+f"(c0), "+f"(c1), "+f"(c2), "+f"(c3)
        : "r"(a0), "r"(a1), "r"(a2), "r"(a3), "r"(b0), "r"(b1));
}

#define DECLARE_POLY_CONSTS                                                        \
    const u64 PA0 = pack2(A0f, A0f), PA1 = pack2(A1f, A1f), PA2 = pack2(A2f, A2f); \
    const u64 PA3 = pack2(A3f, A3f), PA4 = pack2(A4f, A4f), PA5 = pack2(A5f, A5f); \
    const u64 PA6 = pack2(A6f, A6f);

#define DIRP_ARGS(dpi, a0v, a1v)                                               \
    {                                                                          \
        ulonglong2 u1 = *reinterpret_cast<const ulonglong2*>(&D1p[dpi]);       \
        ulonglong2 u2 = *reinterpret_cast<const ulonglong2*>(&D2p[dpi]);       \
        u64 dp2 = fma2(u1.x, nxx, fma2(u1.y, nyy, mul2(u2.x, nzz)));           \
        u64 h2 = fma2(PA6, dp2, PA5);                                          \
        h2 = fma2(h2, dp2, PA4);                                               \
        h2 = fma2(h2, dp2, PA3);                                               \
        h2 = fma2(h2, dp2, PA2);                                               \
        h2 = fma2(h2, dp2, PA1);                                               \
        h2 = fma2(h2, dp2, PA0);                                               \
        float h0, h1; unpack2(h2, h0, h1);                                     \
        float lsw0, lsw1; unpack2(u2.y, lsw0, lsw1);                           \
        a0v = fmaf(fmaxf(h0, HMIN), -K16LOG2E, lsw0);                          \
        a1v = fmaf(fmaxf(h1, HMIN), -K16LOG2E, lsw1);                          \
    }

__global__ __launch_bounds__(BLOCK, 6)
void sh_nearfield_kernel(const float* __restrict__ bases,
                         const float* __restrict__ th,
                         const float* __restrict__ ph,
                         const int*   __restrict__ iternum_p,
                         int B,
                         float* __restrict__ out)
{
    __shared__ __align__(16) float4 D1p[NDIR / 2];
    __shared__ __align__(16) float4 D2p[NDIR / 2];
    __shared__ u32 basesM[32 * BSTRIDE];
    __shared__ u32 lgS[4 * CHUNK * LSTRIDE];

    const int tid  = threadIdx.x;
    const int w    = tid >> 5;
    const int lane = tid & 31;
    const int g    = lane >> 2;
    const int t4   = lane & 3;

    if (tid < NDIR / 2) {
        int d0 = 2 * tid, d1 = 2 * tid + 1;
        float t0 = th[d0], p0f = ph[d0];
        float t1 = th[d1], p1f = ph[d1];
        float st0 = sinf(t0), ct0 = cosf(t0), sp0 = sinf(p0f), cp0 = cosf(p0f);
        float st1 = sinf(t1), ct1 = cosf(t1), sp1 = sinf(p1f), cp1 = cosf(p1f);
        D1p[tid] = make_float4(st0 * sp0, st1 * sp1, ct0, ct1);
        D2p[tid] = make_float4(st0 * cp0, st1 * cp1, log2f(st0), log2f(st1));
    }
    for (int i = tid; i < 32 * NDIR; i += BLOCK) {
        int m = i >> 7, d = i & (NDIR - 1);
        float v = (m < NK) ? bases[m * NDIR + d] : 0.0f;
        basesM[m * BSTRIDE + d] = tf32b(v);
    }
    __syncthreads();

    const int b = blockIdx.z;
    // half-grid point: iy in [0, 64)
    const int ph_idx = blockIdx.x * BLOCK + tid;
    const int ix = ph_idx & (NGRID - 1);
    const int iy = (ph_idx >> 7) & 63;
    const int iz = ph_idx >> 13;

    const int iternum = *iternum_p;
    const float ph0 = (float)((double)(iternum * B + b) * 2.0 * 3.1415926 / 131.0);
    const float lx = sinf(ph0) * 0.3f;
    const float lz = 0.4f;
    const float step = 2.0f / 127.0f;

    float sv;
    u64 nxx, nyy, nzz;
    {
        float x = -1.0f + ix * step;
        float y = -1.0f + iy * step;
        float z = -1.0f + iz * step;
        float ldx = lx - x, ldy = -y, ldz = lz - z;
        float s = fmaf(ldx, ldx, fmaf(ldy, ldy, fmaf(ldz, ldz, 1e-4f)));
        float rn = rsqrtf(s);
        float nx = ldx * rn, ny = ldy * rn, nz = ldz * rn;
        nxx = pack2(nx, nx);
        nyy = pack2(ny, ny);
        nzz = pack2(nz, nz);
        sv = s;
    }

    DECLARE_POLY_CONSTS;

    // ---- Pass 1: normalization sum (4 independent accumulator chains) ----
    float sA = 0.0f, sB = 0.0f, sC2 = 0.0f, sD = 0.0f;
    #pragma unroll 4
    for (int dpi = 0; dpi < NDIR / 2; dpi += 2) {
        float a0, a1, a2, a3;
        DIRP_ARGS(dpi, a0, a1);
        DIRP_ARGS(dpi + 1, a2, a3);
        sA += ex2f(a0);
        sB += ex2f(a1);
        sC2 += ex2f(a2);
        sD += ex2f(a3);
    }
    const float sum = (sA + sB) + (sC2 + sD);
    const float invs = 4.0f / (sv * sum);

    // ---- Pass 2: weights -> lg -> tensor-core projection ----
    float C[2][4][4];
    #pragma unroll
    for (int mt = 0; mt < 2; ++mt)
        #pragma unroll
        for (int nt = 0; nt < 4; ++nt)
            #pragma unroll
            for (int q = 0; q < 4; ++q) C[mt][nt][q] = 0.0f;

    u32* lgW = &lgS[w * CHUNK * LSTRIDE];

    for (int ch = 0; ch < NCH; ++ch) {
        #pragma unroll
        for (int dl = 0; dl < CHUNK / 2; ++dl) {
            int dpi = ch * (CHUNK / 2) + dl;
            float a0, a1;
            DIRP_ARGS(dpi, a0, a1);
            float w0 = ex2f(a0);
            float w1 = ex2f(a1);
            float lg0 = lg2f(fmaf(w0, invs, 1e-4f));
            float lg1 = lg2f(fmaf(w1, invs, 1e-4f));
            lgW[(2 * dl)     * LSTRIDE + lane] = tf32b(lg0);
            lgW[(2 * dl + 1) * LSTRIDE + lane] = tf32b(lg1);
        }
        __syncwarp();

        #pragma unroll
        for (int ks = 0; ks < 2; ++ks) {
            const int kcol = ch * CHUNK + ks * 8 + t4;
            u32 a[2][4];
            #pragma unroll
            for (int mt = 0; mt < 2; ++mt) {
                int base = (g + 16 * mt) * BSTRIDE + kcol;
                a[mt][0] = basesM[base];
                a[mt][1] = basesM[base + 8 * BSTRIDE];
                a[mt][2] = basesM[base + 4];
                a[mt][3] = basesM[base + 8 * BSTRIDE + 4];
            }
            #pragma unroll
            for (int nt = 0; nt < 4; ++nt) {
                int bb = (ks * 8 + t4) * LSTRIDE + 8 * nt + g;
                u32 b0 = lgW[bb];
                u32 b1 = lgW[bb + 4 * LSTRIDE];
                mma_tf32(C[0][nt][0], C[0][nt][1], C[0][nt][2], C[0][nt][3],
                         a[0][0], a[0][1], a[0][2], a[0][3], b0, b1);
                mma_tf32(C[1][nt][0], C[1][nt][1], C[1][nt][2], C[1][nt][3],
                         a[1][0], a[1][1], a[1][2], a[1][3], b0, b1);
            }
        }
        __syncwarp();
    }

    // ---- Epilogue: pair lanes (t4 even|odd) -> STG.128; write both y-mirror rows ----
    const size_t PP = (size_t)P_TOTAL;
    float* ob = out + (size_t)b * 75 * PP;

    const int pb   = blockIdx.x * BLOCK + 32 * w;
    const int ixw  = pb & (NGRID - 1);
    const int iyzw = pb >> 7;
    const int iyv  = iyzw & 63;
    const int izv  = iyzw >> 6;
    const size_t o_lo = (size_t)izv * (NGRID * NGRID) + (size_t)iyv * NGRID + ixw;
    const size_t o_hi = (size_t)izv * (NGRID * NGRID) + (size_t)(127 - iyv) * NGRID + ixw;

    #pragma unroll
    for (int mt = 0; mt < 2; ++mt) {
        #pragma unroll
        for (int nt = 0; nt < 4; ++nt) {
            const int r0 = 16 * mt + g;
            const int r1 = r0 + 8;
            float2 v0 = make_float2(C[mt][nt][0] * SCALE_LN2, C[mt][nt][1] * SCALE_LN2);
            float2 v1 = make_float2(C[mt][nt][2] * SCALE_LN2, C[mt][nt][3] * SCALE_LN2);
            // gather odd-partner's pair into even lanes
            float p0x = __shfl_down_sync(0xFFFFFFFFu, v0.x, 1);
            float p0y = __shfl_down_sync(0xFFFFFFFFu, v0.y, 1);
            float p1x = __shfl_down_sync(0xFFFFFFFFu, v1.x, 1);
            float p1y = __shfl_down_sync(0xFFFFFFFFu, v1.y, 1);
            if (!(t4 & 1)) {
                const int po = 8 * nt + 2 * t4;       // t4 in {0,2} -> cols 0..3 / 4..7
                float sg0 = SGN25[r0];
                float4 q0  = make_float4(v0.x, v0.y, p0x, p0y);
                float4 q0m = make_float4(q0.x * sg0, q0.y * sg0, q0.z * sg0, q0.w * sg0);
                #pragma unroll
                for (int c = 0; c < 3; ++c) {
                    size_t ro = (size_t)(3 * r0 + c) * PP;
                    *reinterpret_cast<float4*>(ob + ro + o_lo + po) = q0;
                    *reinterpret_cast<float4*>(ob + ro + o_hi + po) = q0m;
                }
                if (r1 < NK) {
                    float sg1 = SGN25[r1];
                    float4 q1  = make_float4(v1.x, v1.y, p1x, p1y);
                    float4 q1m = make_float4(q1.x * sg1, q1.y * sg1, q1.z * sg1, q1.w * sg1);
                    #pragma unroll
                    for (int c = 0; c < 3; ++c) {
                        size_t ro = (size_t)(3 * r1 + c) * PP;
                        *reinterpret_cast<float4*>(ob + ro + o_lo + po) = q1;
                        *reinterpret_cast<float4*>(ob + ro + o_hi + po) = q1m;
                    }
                }
            }
        }
    }
}

extern "C" void kernel_launch(void* const* d_in, const int* in_sizes, int n_in,
                              void* d_out, int out_size)
{
    const float* bases = (const float*)d_in[0];
    const float* th    = (const float*)d_in[1];
    const float* ph    = (const float*)d_in[2];
    const int*   itn   = (const int*)d_in[3];
    const int    B     = in_sizes[4];

    dim3 grid(P_TOTAL / (BLOCK * 2), 1, (unsigned)B);
    sh_nearfield_kernel<<<grid, BLOCK>>>(bases, th, ph, itn, B, (float*)d_out);
}

// round 16
// speedup vs baseline: 1.9651x; 1.2196x over previous
#include <cuda_runtime.h>
#include <cuda_bf16.h>
#include <math.h>

#define NGRID 128
#define NDIR  128
#define NK    25
#define P_TOTAL (NGRID*NGRID*NGRID)
#define BLOCK 128
#define CHUNK 16
#define NCH   (NDIR/CHUNK)

#define SCALE_LN2  0.05344600f      // (pi^2/128) * ln2
#define K16LOG2E   23.0831207f      // 16*log2(e)
#define HMIN       0.00200033f      // acos(0.999)^2

// h(x) ~ acos(x)^2, degree-6 monomial
#define A0f  2.46613525f
#define A1f -3.12988405f
#define A2f  0.95262957f
#define A3f -0.41216060f
#define A4f  0.16084943f
#define A5f -0.04312660f
#define A6f  0.00555700f

#define BSTRIDE 132   // bases smem row stride
#define LSTRIDE 40    // lg smem row stride (32 cols + 8 pad; conflict-free)
#define TSTRIDE 34    // epilogue transpose buffer stride (EVEN -> float2-aligned)

typedef unsigned long long u64;
typedef unsigned int u32;

// sign of out_k under y-mirror: (-1)^(n+|m|), k = 0..24
__constant__ float SGN25[25] = {
    1.f,
    1.f,-1.f,1.f,
    1.f,-1.f,1.f,-1.f,1.f,
    1.f,-1.f,1.f,-1.f,1.f,-1.f,1.f,
    1.f,-1.f,1.f,-1.f,1.f,-1.f,1.f,-1.f,1.f
};

__device__ __forceinline__ float ex2f(float x) {
    float r; asm("ex2.approx.ftz.f32 %0, %1;" : "=f"(r) : "f"(x)); return r;
}
__device__ __forceinline__ float lg2f(float x) {
    float r; asm("lg2.approx.ftz.f32 %0, %1;" : "=f"(r) : "f"(x)); return r;
}
__device__ __forceinline__ u64 pack2(float lo, float hi) {
    u64 r; asm("mov.b64 %0, {%1, %2};" : "=l"(r) : "f"(lo), "f"(hi)); return r;
}
__device__ __forceinline__ void unpack2(u64 v, float& lo, float& hi) {
    asm("mov.b64 {%0, %1}, %2;" : "=f"(lo), "=f"(hi) : "l"(v));
}
__device__ __forceinline__ u64 fma2(u64 a, u64 b, u64 c) {
    u64 d; asm("fma.rn.f32x2 %0, %1, %2, %3;" : "=l"(d) : "l"(a), "l"(b), "l"(c)); return d;
}
__device__ __forceinline__ u64 mul2(u64 a, u64 b) {
    u64 d; asm("mul.rn.f32x2 %0, %1, %2;" : "=l"(d) : "l"(a), "l"(b)); return d;
}
__device__ __forceinline__ u32 tf32b(float x) {
    u32 r; asm("cvt.rna.tf32.f32 %0, %1;" : "=r"(r) : "f"(x)); return r;
}
__device__ __forceinline__ void mma_tf32(float& c0, float& c1, float& c2, float& c3,
                                         u32 a0, u32 a1, u32 a2, u32 a3,
                                         u32 b0, u32 b1) {
    asm("mma.sync.aligned.m16n8k8.row.col.f32.tf32.tf32.f32 "
        "{%0,%1,%2,%3}, {%4,%5,%6,%7}, {%8,%9}, {%0,%1,%2,%3};"
        : "+f"(c0), "+f"(c1), "+f"(c2), "+f"(c3)
        : "r"(a0), "r"(a1), "r"(a2), "r"(a3), "r"(b0), "r"(b1));
}

#define DECLARE_POLY_CONSTS                                                        \
    const u64 PA0 = pack2(A0f, A0f), PA1 = pack2(A1f, A1f), PA2 = pack2(A2f, A2f); \
    const u64 PA3 = pack2(A3f, A3f), PA4 = pack2(A4f, A4f), PA5 = pack2(A5f, A5f); \
    const u64 PA6 = pack2(A6f, A6f);

#define DIRP_ARGS(dpi, a0v, a1v)                                               \
    {                                                                          \
        ulonglong2 u1 = *reinterpret_cast<const ulonglong2*>(&D1p[dpi]);       \
        ulonglong2 u2 = *reinterpret_cast<const ulonglong2*>(&D2p[dpi]);       \
        u64 dp2 = fma2(u1.x, nxx, fma2(u1.y, nyy, mul2(u2.x, nzz)));           \
        u64 h2 = fma2(PA6, dp2, PA5);                                          \
        h2 = fma2(h2, dp2, PA4);                                               \
        h2 = fma2(h2, dp2, PA3);                                               \
        h2 = fma2(h2, dp2, PA2);                                               \
        h2 = fma2(h2, dp2, PA1);                                               \
        h2 = fma2(h2, dp2, PA0);                                               \
        float h0, h1; unpack2(h2, h0, h1);                                     \
        float lsw0, lsw1; unpack2(u2.y, lsw0, lsw1);                           \
        a0v = fmaf(fmaxf(h0, HMIN), -K16LOG2E, lsw0);                          \
        a1v = fmaf(fmaxf(h1, HMIN), -K16LOG2E, lsw1);                          \
    }

__global__ __launch_bounds__(BLOCK, 6)
void sh_nearfield_kernel(const float* __restrict__ bases,
                         const float* __restrict__ th,
                         const float* __restrict__ ph,
                         const int*   __restrict__ iternum_p,
                         int B,
                         float* __restrict__ out)
{
    __shared__ __align__(16) float4 D1p[NDIR / 2];
    __shared__ __align__(16) float4 D2p[NDIR / 2];
    __shared__ u32 basesM[32 * BSTRIDE];
    __shared__ __align__(16) u32 lgS[4 * CHUNK * LSTRIDE];

    const int tid  = threadIdx.x;
    const int w    = tid >> 5;
    const int lane = tid & 31;
    const int g    = lane >> 2;
    const int t4   = lane & 3;

    if (tid < NDIR / 2) {
        int d0 = 2 * tid, d1 = 2 * tid + 1;
        float t0 = th[d0], p0f = ph[d0];
        float t1 = th[d1], p1f = ph[d1];
        float st0 = sinf(t0), ct0 = cosf(t0), sp0 = sinf(p0f), cp0 = cosf(p0f);
        float st1 = sinf(t1), ct1 = cosf(t1), sp1 = sinf(p1f), cp1 = cosf(p1f);
        D1p[tid] = make_float4(st0 * sp0, st1 * sp1, ct0, ct1);
        D2p[tid] = make_float4(st0 * cp0, st1 * cp1, log2f(st0), log2f(st1));
    }
    for (int i = tid; i < 32 * NDIR; i += BLOCK) {
        int m = i >> 7, d = i & (NDIR - 1);
        float v = (m < NK) ? bases[m * NDIR + d] : 0.0f;
        basesM[m * BSTRIDE + d] = tf32b(v);
    }
    __syncthreads();

    const int b = blockIdx.z;
    // half-grid point: iy in [0, 64)
    const int ph_idx = blockIdx.x * BLOCK + tid;
    const int ix = ph_idx & (NGRID - 1);
    const int iy = (ph_idx >> 7) & 63;
    const int iz = ph_idx >> 13;

    const int iternum = *iternum_p;
    const float ph0 = (float)((double)(iternum * B + b) * 2.0 * 3.1415926 / 131.0);
    const float lx = sinf(ph0) * 0.3f;
    const float lz = 0.4f;
    const float step = 2.0f / 127.0f;

    float sv;
    u64 nxx, nyy, nzz;
    {
        float x = -1.0f + ix * step;
        float y = -1.0f + iy * step;
        float z = -1.0f + iz * step;
        float ldx = lx - x, ldy = -y, ldz = lz - z;
        float s = fmaf(ldx, ldx, fmaf(ldy, ldy, fmaf(ldz, ldz, 1e-4f)));
        float rn = rsqrtf(s);
        float nx = ldx * rn, ny = ldy * rn, nz = ldz * rn;
        nxx = pack2(nx, nx);
        nyy = pack2(ny, ny);
        nzz = pack2(nz, nz);
        sv = s;
    }

    DECLARE_POLY_CONSTS;

    // ---- Pass 1: normalization sum (4 independent accumulator chains) ----
    float sA = 0.0f, sB = 0.0f, sC2 = 0.0f, sD = 0.0f;
    #pragma unroll 4
    for (int dpi = 0; dpi < NDIR / 2; dpi += 2) {
        float a0, a1, a2, a3;
        DIRP_ARGS(dpi, a0, a1);
        DIRP_ARGS(dpi + 1, a2, a3);
        sA += ex2f(a0);
        sB += ex2f(a1);
        sC2 += ex2f(a2);
        sD += ex2f(a3);
    }
    const float sum = (sA + sB) + (sC2 + sD);
    const float invs = 4.0f / (sv * sum);

    // ---- Pass 2: weights -> lg -> tensor-core projection ----
    float C[2][4][4];
    #pragma unroll
    for (int mt = 0; mt < 2; ++mt)
        #pragma unroll
        for (int nt = 0; nt < 4; ++nt)
            #pragma unroll
            for (int q = 0; q < 4; ++q) C[mt][nt][q] = 0.0f;

    u32* lgW = &lgS[w * CHUNK * LSTRIDE];

    for (int ch = 0; ch < NCH; ++ch) {
        #pragma unroll
        for (int dl = 0; dl < CHUNK / 2; ++dl) {
            int dpi = ch * (CHUNK / 2) + dl;
            float a0, a1;
            DIRP_ARGS(dpi, a0, a1);
            float w0 = ex2f(a0);
            float w1 = ex2f(a1);
            float lg0 = lg2f(fmaf(w0, invs, 1e-4f));
            float lg1 = lg2f(fmaf(w1, invs, 1e-4f));
            lgW[(2 * dl)     * LSTRIDE + lane] = tf32b(lg0);
            lgW[(2 * dl + 1) * LSTRIDE + lane] = tf32b(lg1);
        }
        __syncwarp();

        #pragma unroll
        for (int ks = 0; ks < 2; ++ks) {
            const int kcol = ch * CHUNK + ks * 8 + t4;
            u32 a[2][4];
            #pragma unroll
            for (int mt = 0; mt < 2; ++mt) {
                int base = (g + 16 * mt) * BSTRIDE + kcol;
                a[mt][0] = basesM[base];
                a[mt][1] = basesM[base + 8 * BSTRIDE];
                a[mt][2] = basesM[base + 4];
                a[mt][3] = basesM[base + 8 * BSTRIDE + 4];
            }
            #pragma unroll
            for (int nt = 0; nt < 4; ++nt) {
                int bb = (ks * 8 + t4) * LSTRIDE + 8 * nt + g;
                u32 b0 = lgW[bb];
                u32 b1 = lgW[bb + 4 * LSTRIDE];
                mma_tf32(C[0][nt][0], C[0][nt][1], C[0][nt][2], C[0][nt][3],
                         a[0][0], a[0][1], a[0][2], a[0][3], b0, b1);
                mma_tf32(C[1][nt][0], C[1][nt][1], C[1][nt][2], C[1][nt][3],
                         a[1][0], a[1][1], a[1][2], a[1][3], b0, b1);
            }
        }
        __syncwarp();
    }

    // ---- Epilogue: transpose C through smem; full-line coalesced stores ----
    const size_t PP = (size_t)P_TOTAL;
    float* ob = out + (size_t)b * 75 * PP;

    const int pb   = blockIdx.x * BLOCK + 32 * w;
    const int ixw  = pb & (NGRID - 1);
    const int iyzw = pb >> 7;
    const int iyv  = iyzw & 63;
    const int izv  = iyzw >> 6;
    const size_t o_lo = (size_t)izv * (NGRID * NGRID) + (size_t)iyv * NGRID + ixw + lane;
    const size_t o_hi = (size_t)izv * (NGRID * NGRID) + (size_t)(127 - iyv) * NGRID + ixw + lane;

    // prescale by output factor (same value stream as before)
    #pragma unroll
    for (int mt = 0; mt < 2; ++mt)
        #pragma unroll
        for (int nt = 0; nt < 4; ++nt)
            #pragma unroll
            for (int q = 0; q < 4; ++q) C[mt][nt][q] *= SCALE_LN2;

    float* tb = reinterpret_cast<float*>(&lgS[w * CHUNK * LSTRIDE]);  // 640 floats/warp, need 544

    // half A: k-rows 0..15 (mt = 0: rows g and g+8)
    #pragma unroll
    for (int nt = 0; nt < 4; ++nt) {
        *reinterpret_cast<float2*>(&tb[g       * TSTRIDE + 8 * nt + 2 * t4]) = make_float2(C[0][nt][0], C[0][nt][1]);
        *reinterpret_cast<float2*>(&tb[(g + 8) * TSTRIDE + 8 * nt + 2 * t4]) = make_float2(C[0][nt][2], C[0][nt][3]);
    }
    __syncwarp();
    #pragma unroll
    for (int r = 0; r < 16; ++r) {
        float v  = tb[r * TSTRIDE + lane];
        float vm = v * SGN25[r];
        #pragma unroll
        for (int c = 0; c < 3; ++c) {
            size_t ro = (size_t)(3 * r + c) * PP;
            ob[ro + o_lo] = v;
            ob[ro + o_hi] = vm;
        }
    }
    __syncwarp();

    // half B: k-rows 16..24 (mt = 1: rows 16+g and 24+g -> buffer rows g, g+8)
    #pragma unroll
    for (int nt = 0; nt < 4; ++nt) {
        *reinterpret_cast<float2*>(&tb[g       * TSTRIDE + 8 * nt + 2 * t4]) = make_float2(C[1][nt][0], C[1][nt][1]);
        *reinterpret_cast<float2*>(&tb[(g + 8) * TSTRIDE + 8 * nt + 2 * t4]) = make_float2(C[1][nt][2], C[1][nt][3]);
    }
    __syncwarp();
    #pragma unroll
    for (int r = 0; r < 9; ++r) {
        const int k = 16 + r;
        float v  = tb[r * TSTRIDE + lane];
        float vm = v * SGN25[k];
        #pragma unroll
        for (int c = 0; c < 3; ++c) {
            size_t ro = (size_t)(3 * k + c) * PP;
            ob[ro + o_lo] = v;
            ob[ro + o_hi] = vm;
        }
    }
}

extern "C" void kernel_launch(void* const* d_in, const int* in_sizes, int n_in,
                              void* d_out, int out_size)
{
    const float* bases = (const float*)d_in[0];
    const float* th    = (const float*)d_in[1];
    const float* ph    = (const float*)d_in[2];
    const int*   itn   = (const int*)d_in[3];
    const int    B     = in_sizes[4];

    dim3 grid(P_TOTAL / (BLOCK * 2), 1, (unsigned)B);
    sh_nearfield_kernel<<<grid, BLOCK>>>(bases, th, ph, itn, B, (float*)d_out);
}